// round 1
// baseline (speedup 1.0000x reference)
#include <cuda_runtime.h>
#include <cstdint>
#include <cstddef>

#define NN 2048      // nodes
#define BB 16        // batch
#define TT 256       // time/feature dim

// ---------------- device scratch (no allocations allowed) ----------------
__device__ float g_xavg[TT * NN];          // [t][n]
__device__ float g_invn[NN];
__device__ float g_xnorm[NN * TT];         // [n][t]
__device__ float g_adj[(size_t)NN * NN];
__device__ float g_nmask[(size_t)NN * NN];
__device__ float g_common[(size_t)NN * NN];
__device__ float g_W[(size_t)NN * NN];     // W, then Wn in-place
__device__ float g_y[(size_t)BB * TT * NN];
__device__ float g_degpart[16 * NN];
__device__ float g_dinv[NN];
__device__ float g_max;

// ---------------- small kernels ----------------
__global__ void k_init() { g_max = 0.0f; }

__global__ void k_colmean(const float* __restrict__ x) {
    int e = blockIdx.x * blockDim.x + threadIdx.x;    // over T*N, [t][n]
    if (e >= TT * NN) return;
    float s = 0.f;
#pragma unroll
    for (int b = 0; b < BB; b++) s += x[(size_t)b * TT * NN + e];
    g_xavg[e] = s * (1.0f / BB);
}

__global__ void k_colnorm() {
    int n = blockIdx.x * blockDim.x + threadIdx.x;
    if (n >= NN) return;
    float s = 0.f;
#pragma unroll 4
    for (int t = 0; t < TT; t++) { float v = g_xavg[t * NN + n]; s = fmaf(v, v, s); }
    float nrm = sqrtf(s);
    g_invn[n] = 1.0f / fmaxf(nrm, 1e-12f);
}

__global__ void k_writenorm() {
    int e = blockIdx.x * blockDim.x + threadIdx.x;    // [t][n] enumeration (coalesced reads)
    if (e >= TT * NN) return;
    int t = e / NN, n = e % NN;
    g_xnorm[(size_t)n * TT + t] = g_xavg[e] * g_invn[n];
}

__global__ void k_nmask() {
    __shared__ float tileT[32][33];
    int bi = blockIdx.y * 32, bj = blockIdx.x * 32;
    int tx = threadIdx.x, ty = threadIdx.y;
    tileT[ty][tx] = g_adj[(size_t)(bj + ty) * NN + bi + tx];   // adj[j][i] tile
    __syncthreads();
    int i = bi + ty, j = bj + tx;
    float a  = g_adj[(size_t)i * NN + j];
    float at = tileT[tx][ty];
    float v = fminf(a + at, 1.0f);
    if (i == j) v = 1.0f;
    g_nmask[(size_t)i * NN + j] = v;
}

__global__ void k_W() {
    size_t e = (size_t)blockIdx.x * blockDim.x + threadIdx.x;
    if (e >= (size_t)NN * NN) return;
    float c = g_common[e];
    float w = 0.f;
    if (g_adj[e] != 0.f && c > 1.0f) {
        float maxc = g_max;
        w = (c / maxc) * c;
    }
    g_W[e] = w;
}

__global__ void k_degpart() {
    int d = blockIdx.x * blockDim.x + threadIdx.x;   // gridDim.x = 8 -> d in [0,2048)
    int chunk = blockIdx.y;                          // 16 chunks of 128 rows
    float s = 0.f;
    int s0 = chunk * 128;
#pragma unroll 4
    for (int r = 0; r < 128; r++) s += g_W[(size_t)(s0 + r) * NN + d];
    g_degpart[chunk * NN + d] = s;
}

__global__ void k_dinv() {
    int d = blockIdx.x * blockDim.x + threadIdx.x;
    if (d >= NN) return;
    float s = 0.f;
#pragma unroll
    for (int c = 0; c < 16; c++) s += g_degpart[c * NN + d];
    g_dinv[d] = (s > 0.f) ? rsqrtf(s) : 0.f;
}

__global__ void k_Wn() {
    size_t e = (size_t)blockIdx.x * blockDim.x + threadIdx.x;
    if (e >= (size_t)NN * NN) return;
    int s = (int)(e / NN), d = (int)(e % NN);
    g_W[e] = g_dinv[s] * g_W[e] * g_dinv[d];
}

// ---------------- templated SGEMM 128x128x8, 256 threads, 8x8 microtile ----------------
// C[M,Nc] = A ( [M,K] or [K,M] if TRANSA ) * B ( [K,Nc] or [Nc,K] if TRANSB )
enum { EPI_PLAIN = 0, EPI_ADJ = 1, EPI_COMMON = 2, EPI_OUT = 3 };

template <bool TRANSA, bool TRANSB, int EPI>
__global__ void __launch_bounds__(256)
sgemm_kernel(const float* __restrict__ A, const float* __restrict__ B,
             float* __restrict__ C,
             int M, int Nc, int K, int lda, int ldb, int ldc,
             size_t strideA, size_t strideB, size_t strideC,
             const float* __restrict__ gumbel, const float* __restrict__ bias)
{
    __shared__ float As[8][128];
    __shared__ float Bs[8][128];
    __shared__ float red[256];

    const int tid = threadIdx.x;
    const int tx = tid & 15, ty = tid >> 4;
    const int m0 = blockIdx.y * 128, n0 = blockIdx.x * 128;

    A += strideA * blockIdx.z;
    B += strideB * blockIdx.z;
    C += strideC * blockIdx.z;

    float acc[8][8];
#pragma unroll
    for (int i = 0; i < 8; i++)
#pragma unroll
        for (int j = 0; j < 8; j++) acc[i][j] = 0.f;

    for (int k0 = 0; k0 < K; k0 += 8) {
        if (TRANSA) {
            int tk = tid >> 5, tm = (tid & 31) << 2;
            float4 v = *(const float4*)(A + (size_t)(k0 + tk) * lda + m0 + tm);
            *(float4*)&As[tk][tm] = v;
        } else {
            int ar = tid >> 1, ac = (tid & 1) << 2;
            float4 v = *(const float4*)(A + (size_t)(m0 + ar) * lda + k0 + ac);
            As[ac + 0][ar] = v.x; As[ac + 1][ar] = v.y;
            As[ac + 2][ar] = v.z; As[ac + 3][ar] = v.w;
        }
        if (TRANSB) {
            int br = tid >> 1, bc = (tid & 1) << 2;
            float4 v = *(const float4*)(B + (size_t)(n0 + br) * ldb + k0 + bc);
            Bs[bc + 0][br] = v.x; Bs[bc + 1][br] = v.y;
            Bs[bc + 2][br] = v.z; Bs[bc + 3][br] = v.w;
        } else {
            int tk = tid >> 5, tn = (tid & 31) << 2;
            float4 v = *(const float4*)(B + (size_t)(k0 + tk) * ldb + n0 + tn);
            *(float4*)&Bs[tk][tn] = v;
        }
        __syncthreads();
#pragma unroll
        for (int kk = 0; kk < 8; kk++) {
            float a[8], b[8];
#pragma unroll
            for (int i = 0; i < 8; i++) a[i] = As[kk][ty * 8 + i];
#pragma unroll
            for (int j = 0; j < 8; j++) b[j] = Bs[kk][tx * 8 + j];
#pragma unroll
            for (int i = 0; i < 8; i++)
#pragma unroll
                for (int j = 0; j < 8; j++) acc[i][j] = fmaf(a[i], b[j], acc[i][j]);
        }
        __syncthreads();
    }

    if (EPI == EPI_ADJ) {
        const float2* g2 = (const float2*)gumbel;
#pragma unroll
        for (int i = 0; i < 8; i++) {
            int r = m0 + ty * 8 + i;
#pragma unroll
            for (int j = 0; j < 8; j++) {
                int c = n0 + tx * 8 + j;
                float sim = (acc[i][j] + 1.0f) * 0.5f;
                float2 g = g2[(size_t)r * Nc + c];
                float s0 = sim + g.x;
                float s1 = (1.0f - sim) + g.y;
                C[(size_t)r * ldc + c] = (s0 > s1) ? 1.0f : 0.0f;
            }
        }
    } else if (EPI == EPI_COMMON) {
        float lmax = 0.f;
#pragma unroll
        for (int i = 0; i < 8; i++) {
            int r = m0 + ty * 8 + i;
#pragma unroll
            for (int j = 0; j < 8; j++) {
                int c = n0 + tx * 8 + j;
                float v = acc[i][j];
                C[(size_t)r * ldc + c] = v;
                lmax = fmaxf(lmax, v);
            }
        }
        red[tid] = lmax;
        __syncthreads();
        for (int s = 128; s > 0; s >>= 1) {
            if (tid < s) red[tid] = fmaxf(red[tid], red[tid + s]);
            __syncthreads();
        }
        if (tid == 0) atomicMax((int*)&g_max, __float_as_int(red[0]));
    } else if (EPI == EPI_OUT) {
#pragma unroll
        for (int i = 0; i < 8; i++) {
            int r = m0 + ty * 8 + i;
            float bv = bias[r & (TT - 1)];
#pragma unroll
            for (int j = 0; j < 8; j++) {
                int c = n0 + tx * 8 + j;
                C[(size_t)r * ldc + c] = acc[i][j] + bv;
            }
        }
    } else {
#pragma unroll
        for (int i = 0; i < 8; i++) {
            int r = m0 + ty * 8 + i;
#pragma unroll
            for (int j = 0; j < 8; j++) {
                int c = n0 + tx * 8 + j;
                C[(size_t)r * ldc + c] = acc[i][j];
            }
        }
    }
}

// ---------------- launcher ----------------
extern "C" void kernel_launch(void* const* d_in, const int* in_sizes, int n_in,
                              void* d_out, int out_size)
{
    const float* x      = (const float*)d_in[0];   // [B,T,N]
    const float* weight = (const float*)d_in[1];   // [T,T]
    const float* bias   = (const float*)d_in[2];   // [T]
    const float* gumbel = (const float*)d_in[3];   // [N*N, 2]
    float* out = (float*)d_out;                    // [B,T,N]

    float *p_xnorm, *p_adj, *p_nmask, *p_common, *p_W, *p_y;
    cudaGetSymbolAddress((void**)&p_xnorm,  g_xnorm);
    cudaGetSymbolAddress((void**)&p_adj,    g_adj);
    cudaGetSymbolAddress((void**)&p_nmask,  g_nmask);
    cudaGetSymbolAddress((void**)&p_common, g_common);
    cudaGetSymbolAddress((void**)&p_W,      g_W);
    cudaGetSymbolAddress((void**)&p_y,      g_y);

    k_init<<<1, 1>>>();

    // mean over batch + row-normalize
    k_colmean<<<(TT * NN) / 256, 256>>>(x);
    k_colnorm<<<NN / 256, 256>>>();
    k_writenorm<<<(TT * NN) / 256, 256>>>();

    // sim GEMM (Xn @ Xn^T) fused with gumbel argmax -> adj
    {
        dim3 grid(NN / 128, NN / 128, 1);
        sgemm_kernel<false, true, EPI_ADJ><<<grid, 256>>>(
            p_xnorm, p_xnorm, p_adj, NN, NN, TT, TT, TT, NN,
            0, 0, 0, gumbel, nullptr);
    }

    // nmask = clip(adj + adj^T, 0, 1) with forced diagonal 1
    {
        dim3 grid(NN / 32, NN / 32);
        dim3 blk(32, 32);
        k_nmask<<<grid, blk>>>();
    }

    // common = nmask @ nmask^T (binary, exact) + global max
    {
        dim3 grid(NN / 128, NN / 128, 1);
        sgemm_kernel<false, true, EPI_COMMON><<<grid, 256>>>(
            p_nmask, p_nmask, p_common, NN, NN, NN, NN, NN, NN,
            0, 0, 0, nullptr, nullptr);
    }

    // W = adj * struct
    k_W<<<(int)(((size_t)NN * NN) / 256), 256>>>();

    // deg (deterministic two-phase column sums), dinv, Wn (in place over g_W)
    {
        dim3 grid(NN / 256, 16);
        k_degpart<<<grid, 256>>>();
    }
    k_dinv<<<NN / 256, 256>>>();
    k_Wn<<<(int)(((size_t)NN * NN) / 256), 256>>>();

    // Y_b[o][n] = sum_t weight[t][o] * x[b][t][n]   (A accessed transposed)
    {
        dim3 grid(NN / 128, TT / 128, BB);
        sgemm_kernel<true, false, EPI_PLAIN><<<grid, 256>>>(
            weight, x, p_y, TT, NN, TT, TT, NN, NN,
            0, (size_t)TT * NN, (size_t)TT * NN, nullptr, nullptr);
    }

    // out[(b*T+t)][d] = sum_s Y[(b*T+t)][s] * Wn[s][d] + bias[t]
    {
        dim3 grid(NN / 128, (BB * TT) / 128, 1);
        sgemm_kernel<false, false, EPI_OUT><<<grid, 256>>>(
            p_y, p_W, out, BB * TT, NN, NN, NN, NN, NN,
            0, 0, 0, nullptr, bias);
    }
}

// round 3
// speedup vs baseline: 2.3203x; 2.3203x over previous
#include <cuda_runtime.h>
#include <cuda_fp16.h>
#include <cstdint>
#include <cstddef>

#define NN 2048      // nodes
#define BB 16        // batch
#define TT 256       // time/feature dim
#define K3 (3*TT)    // 768
#define N3 (3*NN)    // 6144

// ---------------- device scratch (no allocations allowed) ----------------
__device__ float g_xavg[TT * NN];                 // [t][n]
__device__ float g_invn[NN];
__device__ __half g_xa3[(size_t)NN * K3];         // [n][768] = [h, l, h]
__device__ __half g_xb3[(size_t)NN * K3];         // [n][768] = [h, h, l]
__device__ float g_adj[(size_t)NN * NN];
__device__ __half g_nmb[(size_t)NN * NN];         // nmask fp16 (exact 0/1)
__device__ float g_common[(size_t)NN * NN];
__device__ float g_M[(size_t)NN * NN];            // M = adj*(c>1)*c^2  (exact integers)
__device__ __half g_WT3[(size_t)NN * N3];         // [d][6144] = [Mh*16, Ml, M/128]
__device__ __half g_Y3[(size_t)BB * TT * N3];     // [4096][6144] = [Yh*128, Yh, Yl*128]
__device__ float g_degpart[16 * NN];
__device__ float g_dinv[NN];
__device__ float g_max;

// ---------------- PTX helpers (sm_80-level features only) ----------------
__device__ __forceinline__ uint32_t smem_u32(const void* p) {
    uint32_t a;
    asm("{ .reg .u64 t; cvta.to.shared.u64 t, %1; cvt.u32.u64 %0, t; }"
        : "=r"(a) : "l"(p));
    return a;
}

#define CP16(dst, src) \
    asm volatile("cp.async.cg.shared.global [%0], [%1], 16;" :: "r"(dst), "l"(src))
#define CP_COMMIT() asm volatile("cp.async.commit_group;" ::: "memory")
#define CP_WAIT0()  asm volatile("cp.async.wait_group 0;" ::: "memory")
#define CP_WAIT1()  asm volatile("cp.async.wait_group 1;" ::: "memory")

__device__ __forceinline__ void ldsm_x4(uint32_t& r0, uint32_t& r1, uint32_t& r2,
                                        uint32_t& r3, uint32_t addr) {
    asm volatile("ldmatrix.sync.aligned.m8n8.x4.shared.b16 {%0,%1,%2,%3}, [%4];"
                 : "=r"(r0), "=r"(r1), "=r"(r2), "=r"(r3) : "r"(addr));
}

__device__ __forceinline__ void mma16816(float* c, const uint32_t* a, const uint32_t* b) {
    asm volatile(
        "mma.sync.aligned.m16n8k16.row.col.f32.f16.f16.f32 "
        "{%0,%1,%2,%3}, {%4,%5,%6,%7}, {%8,%9}, {%0,%1,%2,%3};"
        : "+f"(c[0]), "+f"(c[1]), "+f"(c[2]), "+f"(c[3])
        : "r"(a[0]), "r"(a[1]), "r"(a[2]), "r"(a[3]), "r"(b[0]), "r"(b[1]));
}

// ---------------- small kernels ----------------
__global__ void k_init() { g_max = 0.0f; }

__global__ void k_colmean(const float* __restrict__ x) {
    int e = blockIdx.x * blockDim.x + threadIdx.x;    // over T*N, [t][n]
    if (e >= TT * NN) return;
    float s = 0.f;
#pragma unroll
    for (int b = 0; b < BB; b++) s += x[(size_t)b * TT * NN + e];
    g_xavg[e] = s * (1.0f / BB);
}

__global__ void k_colnorm() {
    int n = blockIdx.x * blockDim.x + threadIdx.x;
    if (n >= NN) return;
    float s = 0.f;
#pragma unroll 4
    for (int t = 0; t < TT; t++) { float v = g_xavg[t * NN + n]; s = fmaf(v, v, s); }
    float nrm = sqrtf(s);
    g_invn[n] = 1.0f / fmaxf(nrm, 1e-12f);
}

__global__ void k_writenorm() {
    int e = blockIdx.x * blockDim.x + threadIdx.x;    // [t][n]
    if (e >= TT * NN) return;
    int t = e / NN, n = e % NN;
    float v = g_xavg[e] * g_invn[n];
    __half h = __float2half_rn(v);
    __half l = __float2half_rn(v - __half2float(h));
    size_t base = (size_t)n * K3;
    g_xa3[base + t] = h; g_xa3[base + TT + t] = l; g_xa3[base + 2 * TT + t] = h;
    g_xb3[base + t] = h; g_xb3[base + TT + t] = h; g_xb3[base + 2 * TT + t] = l;
}

__global__ void k_nmask() {
    __shared__ float tileT[32][33];
    int bi = blockIdx.y * 32, bj = blockIdx.x * 32;
    int tx = threadIdx.x, ty = threadIdx.y;
    tileT[ty][tx] = g_adj[(size_t)(bj + ty) * NN + bi + tx];   // adj[j][i] tile
    __syncthreads();
    int i = bi + ty, j = bj + tx;
    float a  = g_adj[(size_t)i * NN + j];
    float at = tileT[tx][ty];
    float v = fminf(a + at, 1.0f);
    if (i == j) v = 1.0f;
    g_nmb[(size_t)i * NN + j] = __float2half_rn(v);   // exact 0/1
}

// M = (adj && c>1) ? c*c : 0   (exact integer <= 2^22 in fp32)
__global__ void k_M() {
    size_t e = (size_t)blockIdx.x * blockDim.x + threadIdx.x;
    if (e >= (size_t)NN * NN) return;
    float c = g_common[e];
    float m = 0.f;
    if (g_adj[e] != 0.f && c > 1.0f) m = c * c;
    g_M[e] = m;
}

__global__ void k_degpart() {
    int d = blockIdx.x * blockDim.x + threadIdx.x;
    int chunk = blockIdx.y;
    float s = 0.f;
    int s0 = chunk * 128;
#pragma unroll 4
    for (int r = 0; r < 128; r++) s += g_M[(size_t)(s0 + r) * NN + d];
    g_degpart[chunk * NN + d] = s;
}

__global__ void k_dinv() {
    int d = blockIdx.x * blockDim.x + threadIdx.x;
    if (d >= NN) return;
    float s = 0.f;
#pragma unroll
    for (int c = 0; c < 16; c++) s += g_degpart[c * NN + d];
    float deg = s / g_max;
    g_dinv[d] = (deg > 0.f) ? rsqrtf(deg) : 0.f;
}

// transpose M -> WT3 [d][6144] = [Mh*16, Ml, M/128]; Mh=floor(M/2048), Ml=M-2048*Mh
__global__ void k_wt3() {
    __shared__ float tile[32][33];
    int bs = blockIdx.y * 32, bd = blockIdx.x * 32;
    int tx = threadIdx.x, ty = threadIdx.y;
    tile[ty][tx] = g_M[(size_t)(bs + ty) * NN + bd + tx];
    __syncthreads();
    float v = tile[tx][ty];              // M[bs+tx][bd+ty]
    float mh = floorf(v * (1.0f / 2048.0f));     // exact
    float ml = v - mh * 2048.0f;                 // exact, < 2048
    size_t base = (size_t)(bd + ty) * N3 + bs + tx;
    g_WT3[base]          = __float2half_rn(mh * 16.0f);      // exact
    g_WT3[base + NN]     = __float2half_rn(ml);              // exact
    g_WT3[base + 2 * NN] = __float2half_rn(v * (1.0f / 128.0f)); // rel err 2^-12
}

// ---------------- HMMA fp16 GEMM: 128x128 tile, 8 warps, k-chunk 32 ----------------
// C[m,n] = sum_k A[m*lda+k] * B[n*ldb+k]  (both operands K-contiguous)
enum { HEPI_ADJ = 0, HEPI_COMMON = 1, HEPI_OUT = 2 };

#define PITCH 40                     // halfs per smem row (80 B, conflict-free ldmatrix)
#define TILE_H (128 * PITCH)         // 5120 halfs
#define TILE_B (TILE_H * 2)          // 10240 bytes

struct alignas(1024) HSmem {
    __half a[2][TILE_H];
    __half b[2][TILE_H];
    float red[256];
};

template <int EPI>
__global__ void __launch_bounds__(256)
hmma_gemm(const __half* __restrict__ A, const __half* __restrict__ B,
          float* __restrict__ C, int K, int lda, int ldb, int ldc,
          const float* __restrict__ gumbel, const float* __restrict__ bias)
{
    __shared__ HSmem sm;
    const int tid = threadIdx.x, lane = tid & 31, wid = tid >> 5;
    const int wm = (wid & 3) * 32;       // warp row offset within tile
    const int wn = (wid >> 2) * 64;      // warp col offset within tile
    const int m0 = blockIdx.y * 128, n0 = blockIdx.x * 128;

    const uint32_t sa0 = smem_u32(sm.a);
    const uint32_t sb0 = smem_u32(sm.b);

    float acc[2][8][4];
#pragma unroll
    for (int i = 0; i < 2; i++)
#pragma unroll
        for (int j = 0; j < 8; j++)
#pragma unroll
            for (int q = 0; q < 4; q++) acc[i][j][q] = 0.f;

    const int nch = K >> 5;
    const int lr = tid >> 2, lu = tid & 3;   // load row (0-63), 16B unit (0-3)

    // prologue: chunk 0 -> buf 0
    {
        const __half* ga = A + (size_t)(m0 + lr) * lda + lu * 8;
        const __half* gb = B + (size_t)(n0 + lr) * ldb + lu * 8;
        uint32_t da = sa0 + lr * 80 + lu * 16;
        uint32_t db = sb0 + lr * 80 + lu * 16;
        CP16(da, ga); CP16(db, gb);
        CP16(da + 64 * 80, ga + (size_t)64 * lda);
        CP16(db + 64 * 80, gb + (size_t)64 * ldb);
        CP_COMMIT();
    }

    for (int c = 0; c < nch; c++) {
        if (c + 1 < nch) {
            int kc = (c + 1) << 5, buf = (c + 1) & 1;
            const __half* ga = A + (size_t)(m0 + lr) * lda + kc + lu * 8;
            const __half* gb = B + (size_t)(n0 + lr) * ldb + kc + lu * 8;
            uint32_t da = sa0 + buf * TILE_B + lr * 80 + lu * 16;
            uint32_t db = sb0 + buf * TILE_B + lr * 80 + lu * 16;
            CP16(da, ga); CP16(db, gb);
            CP16(da + 64 * 80, ga + (size_t)64 * lda);
            CP16(db + 64 * 80, gb + (size_t)64 * ldb);
            CP_COMMIT();
            CP_WAIT1();
        } else {
            CP_WAIT0();
        }
        __syncthreads();

        const uint32_t ba = sa0 + (c & 1) * TILE_B;
        const uint32_t bb = sb0 + (c & 1) * TILE_B;
#pragma unroll
        for (int k16 = 0; k16 < 2; k16++) {
            uint32_t a[2][4], b[8][2];
            // A: 2 m-tiles (m16k16) via ldmatrix.x4
            {
                int arow = wm + (lane & 15);
                int au = k16 * 2 + (lane >> 4);
                ldsm_x4(a[0][0], a[0][1], a[0][2], a[0][3], ba + arow * 80 + au * 16);
                ldsm_x4(a[1][0], a[1][1], a[1][2], a[1][3], ba + (arow + 16) * 80 + au * 16);
            }
            // B: 8 n-tiles (n8k16), two per ldmatrix.x4
#pragma unroll
            for (int np = 0; np < 4; np++) {
                int brow = wn + np * 16 + (lane & 7) + ((lane >> 4) << 3);
                int bu = k16 * 2 + ((lane >> 3) & 1);
                uint32_t r0, r1, r2, r3;
                ldsm_x4(r0, r1, r2, r3, bb + brow * 80 + bu * 16);
                b[2 * np][0] = r0; b[2 * np][1] = r1;
                b[2 * np + 1][0] = r2; b[2 * np + 1][1] = r3;
            }
#pragma unroll
            for (int mt = 0; mt < 2; mt++)
#pragma unroll
                for (int nt = 0; nt < 8; nt++)
                    mma16816(acc[mt][nt], a[mt], b[nt]);
        }
        __syncthreads();
    }

    // epilogue: element (mt,nt,q): row = m0+wm+mt*16+(lane>>2)+8*(q>>1),
    //                              col = n0+wn+nt*8+2*(lane&3)+(q&1)
    const int g = lane >> 2, tig = lane & 3;
    float lmax = 0.f;
#pragma unroll
    for (int mt = 0; mt < 2; mt++) {
#pragma unroll
        for (int half = 0; half < 2; half++) {
            int row = m0 + wm + mt * 16 + g + half * 8;
#pragma unroll
            for (int nt = 0; nt < 8; nt++) {
                int col = n0 + wn + nt * 8 + 2 * tig;
                float v0 = acc[mt][nt][half * 2 + 0];
                float v1 = acc[mt][nt][half * 2 + 1];
                if (EPI == HEPI_ADJ) {
                    const float2* g2 = (const float2*)gumbel;
                    float2 ga = g2[(size_t)row * NN + col];
                    float2 gb = g2[(size_t)row * NN + col + 1];
                    float s0 = (v0 + 1.0f) * 0.5f;
                    float s1 = (v1 + 1.0f) * 0.5f;
                    C[(size_t)row * ldc + col]     = (s0 + ga.x > (1.0f - s0) + ga.y) ? 1.0f : 0.0f;
                    C[(size_t)row * ldc + col + 1] = (s1 + gb.x > (1.0f - s1) + gb.y) ? 1.0f : 0.0f;
                } else if (EPI == HEPI_COMMON) {
                    C[(size_t)row * ldc + col]     = v0;
                    C[(size_t)row * ldc + col + 1] = v1;
                    lmax = fmaxf(lmax, fmaxf(v0, v1));
                } else {
                    float sc = 1.0f / g_max;
                    float bv = bias[row & (TT - 1)];
                    float2 o;
                    o.x = v0 * (g_dinv[col] * sc) + bv;
                    o.y = v1 * (g_dinv[col + 1] * sc) + bv;
                    *(float2*)&C[(size_t)row * ldc + col] = o;
                }
            }
        }
    }
    if (EPI == HEPI_COMMON) {
        sm.red[tid] = lmax;
        __syncthreads();
        for (int s = 128; s > 0; s >>= 1) {
            if (tid < s) sm.red[tid] = fmaxf(sm.red[tid], sm.red[tid + s]);
            __syncthreads();
        }
        if (tid == 0) atomicMax((int*)&g_max, __float_as_int(sm.red[0]));
    }
}

// ---------------- FFMA SGEMM for xw (K=256), epilogue writes Y3 split ----------------
__global__ void __launch_bounds__(256)
sgemm_y3(const float* __restrict__ A,   // weight [T][T], accessed transposed
         const float* __restrict__ B,   // x [B][T][N]
         int lda, int ldb)
{
    __shared__ float As[8][128];
    __shared__ float Bs[8][128];

    const int tid = threadIdx.x;
    const int tx = tid & 15, ty = tid >> 4;
    const int m0 = blockIdx.y * 128, n0 = blockIdx.x * 128;
    const int z = blockIdx.z;

    B += (size_t)z * TT * NN;

    float acc[8][8];
#pragma unroll
    for (int i = 0; i < 8; i++)
#pragma unroll
        for (int j = 0; j < 8; j++) acc[i][j] = 0.f;

    for (int k0 = 0; k0 < TT; k0 += 8) {
        {   // A transposed load: As[k][m] = A[k][m]
            int tk = tid >> 5, tm = (tid & 31) << 2;
            float4 v = *(const float4*)(A + (size_t)(k0 + tk) * lda + m0 + tm);
            *(float4*)&As[tk][tm] = v;
        }
        {
            int tk = tid >> 5, tn = (tid & 31) << 2;
            float4 v = *(const float4*)(B + (size_t)(k0 + tk) * ldb + n0 + tn);
            *(float4*)&Bs[tk][tn] = v;
        }
        __syncthreads();
#pragma unroll
        for (int kk = 0; kk < 8; kk++) {
            float a[8], b[8];
#pragma unroll
            for (int i = 0; i < 8; i++) a[i] = As[kk][ty * 8 + i];
#pragma unroll
            for (int j = 0; j < 8; j++) b[j] = Bs[kk][tx * 8 + j];
#pragma unroll
            for (int i = 0; i < 8; i++)
#pragma unroll
                for (int j = 0; j < 8; j++) acc[i][j] = fmaf(a[i], b[j], acc[i][j]);
        }
        __syncthreads();
    }

    // write Y3[(z*TT + o)][6144] = [Yh*128, Yh, Yl*128], Y' = acc * dinv[col]
    __half* O = g_Y3 + (size_t)z * TT * N3;
#pragma unroll
    for (int i = 0; i < 8; i++) {
        int r = m0 + ty * 8 + i;
        size_t base = (size_t)r * N3;
#pragma unroll
        for (int j = 0; j < 8; j++) {
            int c = n0 + tx * 8 + j;
            float yp = acc[i][j] * g_dinv[c];
            __half h = __float2half_rn(yp);
            float hf = __half2float(h);
            __half l128 = __float2half_rn((yp - hf) * 128.0f);
            O[base + c]          = __float2half_rn(hf * 128.0f);  // exact
            O[base + NN + c]     = h;
            O[base + 2 * NN + c] = l128;
        }
    }
}

// ---------------- launcher ----------------
extern "C" void kernel_launch(void* const* d_in, const int* in_sizes, int n_in,
                              void* d_out, int out_size)
{
    const float* x      = (const float*)d_in[0];   // [B,T,N]
    const float* weight = (const float*)d_in[1];   // [T,T]
    const float* bias   = (const float*)d_in[2];   // [T]
    const float* gumbel = (const float*)d_in[3];   // [N*N, 2]
    float* out = (float*)d_out;                    // [B,T,N] = [4096][2048]

    __half *p_xa3, *p_xb3, *p_nmb, *p_wt3, *p_y3;
    float *p_adj, *p_common;
    cudaGetSymbolAddress((void**)&p_xa3,    g_xa3);
    cudaGetSymbolAddress((void**)&p_xb3,    g_xb3);
    cudaGetSymbolAddress((void**)&p_nmb,    g_nmb);
    cudaGetSymbolAddress((void**)&p_wt3,    g_WT3);
    cudaGetSymbolAddress((void**)&p_y3,     g_Y3);
    cudaGetSymbolAddress((void**)&p_adj,    g_adj);
    cudaGetSymbolAddress((void**)&p_common, g_common);

    k_init<<<1, 1>>>();

    // mean over batch + row-normalize + fp16 hi/lo split (K-concat)
    k_colmean<<<(TT * NN) / 256, 256>>>(x);
    k_colnorm<<<NN / 256, 256>>>();
    k_writenorm<<<(TT * NN) / 256, 256>>>();

    // sim GEMM (3-term fp16 split, K=768) fused gumbel argmax -> adj
    {
        dim3 grid(NN / 128, NN / 128);
        hmma_gemm<HEPI_ADJ><<<grid, 256>>>(p_xa3, p_xb3, p_adj, K3, K3, K3, NN,
                                           gumbel, nullptr);
    }

    // nmask = clip(adj + adj^T, 0, 1), diag=1, as fp16
    {
        dim3 grid(NN / 32, NN / 32);
        dim3 blk(32, 32);
        k_nmask<<<grid, blk>>>();
    }

    // common = nmask @ nmask^T (binary -> exact) + global max
    {
        dim3 grid(NN / 128, NN / 128);
        hmma_gemm<HEPI_COMMON><<<grid, 256>>>(p_nmb, p_nmb, p_common, NN, NN, NN, NN,
                                              nullptr, nullptr);
    }

    // M = adj * (c>1) * c^2 (exact integers)
    k_M<<<(int)(((size_t)NN * NN) / 256), 256>>>();

    // deg = (sum_s M)/max, dinv
    {
        dim3 grid(NN / 256, 16);
        k_degpart<<<grid, 256>>>();
    }
    k_dinv<<<NN / 256, 256>>>();

    // WT3 = transpose + exact integer split of M
    {
        dim3 grid(NN / 32, NN / 32);
        dim3 blk(32, 32);
        k_wt3<<<grid, blk>>>();
    }

    // Y3[(b,o)][n] = (sum_t weight[t][o] * x[b][t][n]) * dinv[n], split-epilogue
    {
        dim3 grid(NN / 128, TT / 128, BB);
        sgemm_y3<<<grid, 256>>>(weight, x, TT, NN);
    }

    // out = (Y' @ M) * dinv[d]/max + bias  (3-term fp16 K-concat, K=6144)
    {
        dim3 grid(NN / 128, (BB * TT) / 128);
        hmma_gemm<HEPI_OUT><<<grid, 256>>>(p_y3, p_wt3, out, N3, N3, N3, NN,
                                           nullptr, bias);
    }
}

// round 4
// speedup vs baseline: 2.6961x; 1.1620x over previous
#include <cuda_runtime.h>
#include <cuda_fp16.h>
#include <cstdint>
#include <cstddef>

#define NN 2048      // nodes
#define BB 16        // batch
#define TT 256       // time/feature dim
#define K3 (3*TT)    // 768
#define N3 (3*NN)    // 6144

// ---------------- device scratch (no allocations allowed) ----------------
__device__ float g_xavg[TT * NN];                 // [t][n]
__device__ float g_invn[NN];
__device__ __half g_xa3[(size_t)NN * K3];         // [n][768] = [h, l, h]
__device__ __half g_xb3[(size_t)NN * K3];         // [n][768] = [h, h, l]
__device__ __half g_w3[(size_t)TT * K3];          // [o][768] = [wh, wl, wh]
__device__ __half g_xT3[(size_t)BB * NN * K3];    // [b][n][768] = [xh, xh, xl]
__device__ float g_adj[(size_t)NN * NN];
__device__ __half g_nmb[(size_t)NN * NN];         // nmask fp16 (exact 0/1)
__device__ float g_common[(size_t)NN * NN];
__device__ float g_M[(size_t)NN * NN];            // M = adj*(c>1)*c^2 (exact ints)
__device__ __half g_WT3[(size_t)NN * N3];         // [d][6144] = [Mh*16, Ml, M/128]
__device__ __half g_Y3[(size_t)BB * TT * N3];     // [4096][6144] = [Yh*128, Yh, Yl*128]
__device__ float g_degpart[16 * NN];
__device__ float g_dinv[NN];
__device__ float g_max;

// ---------------- PTX helpers (sm_80-level features only) ----------------
__device__ __forceinline__ uint32_t smem_u32(const void* p) {
    uint32_t a;
    asm("{ .reg .u64 t; cvta.to.shared.u64 t, %1; cvt.u32.u64 %0, t; }"
        : "=r"(a) : "l"(p));
    return a;
}

#define CP16(dst, src) \
    asm volatile("cp.async.cg.shared.global [%0], [%1], 16;" :: "r"(dst), "l"(src))
#define CP_COMMIT() asm volatile("cp.async.commit_group;" ::: "memory")
#define CP_WAIT2()  asm volatile("cp.async.wait_group 2;" ::: "memory")

__device__ __forceinline__ void ldsm_x4(uint32_t& r0, uint32_t& r1, uint32_t& r2,
                                        uint32_t& r3, uint32_t addr) {
    asm volatile("ldmatrix.sync.aligned.m8n8.x4.shared.b16 {%0,%1,%2,%3}, [%4];"
                 : "=r"(r0), "=r"(r1), "=r"(r2), "=r"(r3) : "r"(addr));
}

__device__ __forceinline__ void mma16816(float* c, const uint32_t* a, const uint32_t* b) {
    asm volatile(
        "mma.sync.aligned.m16n8k16.row.col.f32.f16.f16.f32 "
        "{%0,%1,%2,%3}, {%4,%5,%6,%7}, {%8,%9}, {%0,%1,%2,%3};"
        : "+f"(c[0]), "+f"(c[1]), "+f"(c[2]), "+f"(c[3])
        : "r"(a[0]), "r"(a[1]), "r"(a[2]), "r"(a[3]), "r"(b[0]), "r"(b[1]));
}

// ---------------- small kernels ----------------
__global__ void k_init() { g_max = 0.0f; }

__global__ void k_colmean(const float* __restrict__ x) {
    int e = blockIdx.x * blockDim.x + threadIdx.x;    // over T*N, [t][n]
    if (e >= TT * NN) return;
    float s = 0.f;
#pragma unroll
    for (int b = 0; b < BB; b++) s += x[(size_t)b * TT * NN + e];
    g_xavg[e] = s * (1.0f / BB);
}

__global__ void k_colnorm() {
    int n = blockIdx.x * blockDim.x + threadIdx.x;
    if (n >= NN) return;
    float s = 0.f;
#pragma unroll 4
    for (int t = 0; t < TT; t++) { float v = g_xavg[t * NN + n]; s = fmaf(v, v, s); }
    float nrm = sqrtf(s);
    g_invn[n] = 1.0f / fmaxf(nrm, 1e-12f);
}

// tiled transpose + split: coalesced reads of xavg, coalesced segment writes
__global__ void k_writenorm() {   // grid (NN/32, TT/32), block (32,32)
    __shared__ float tile[32][33];
    int n0 = blockIdx.x * 32, t0 = blockIdx.y * 32;
    int tx = threadIdx.x, ty = threadIdx.y;
    tile[ty][tx] = g_xavg[(t0 + ty) * NN + n0 + tx] * g_invn[n0 + tx];
    __syncthreads();
    int n = n0 + ty, t = t0 + tx;
    float v = tile[tx][ty];
    __half h = __float2half_rn(v);
    __half l = __float2half_rn(v - __half2float(h));
    size_t base = (size_t)n * K3;
    g_xa3[base + t] = h; g_xa3[base + TT + t] = l; g_xa3[base + 2 * TT + t] = h;
    g_xb3[base + t] = h; g_xb3[base + TT + t] = h; g_xb3[base + 2 * TT + t] = l;
}

// weight [t][o] -> w3 [o][768] = [wh, wl, wh]
__global__ void k_w3(const float* __restrict__ w) {  // grid (8,8), block (32,32)
    __shared__ float tile[32][33];
    int o0 = blockIdx.x * 32, t0 = blockIdx.y * 32;
    int tx = threadIdx.x, ty = threadIdx.y;
    tile[ty][tx] = w[(t0 + ty) * TT + o0 + tx];
    __syncthreads();
    int o = o0 + ty, t = t0 + tx;
    float v = tile[tx][ty];
    __half h = __float2half_rn(v);
    __half l = __float2half_rn(v - __half2float(h));
    size_t base = (size_t)o * K3;
    g_w3[base + t] = h; g_w3[base + TT + t] = l; g_w3[base + 2 * TT + t] = h;
}

// x [b][t][n] -> xT3 [b][n][768] = [xh, xh, xl]
__global__ void k_xt3(const float* __restrict__ x) { // grid (NN/32, TT/32, BB), block (32,32)
    __shared__ float tile[32][33];
    int n0 = blockIdx.x * 32, t0 = blockIdx.y * 32, z = blockIdx.z;
    int tx = threadIdx.x, ty = threadIdx.y;
    tile[ty][tx] = x[(size_t)z * TT * NN + (t0 + ty) * NN + n0 + tx];
    __syncthreads();
    int n = n0 + ty, t = t0 + tx;
    float v = tile[tx][ty];
    __half h = __float2half_rn(v);
    __half l = __float2half_rn(v - __half2float(h));
    size_t base = ((size_t)z * NN + n) * K3;
    g_xT3[base + t] = h; g_xT3[base + TT + t] = h; g_xT3[base + 2 * TT + t] = l;
}

__global__ void k_nmask() {
    __shared__ float tileT[32][33];
    int bi = blockIdx.y * 32, bj = blockIdx.x * 32;
    int tx = threadIdx.x, ty = threadIdx.y;
    tileT[ty][tx] = g_adj[(size_t)(bj + ty) * NN + bi + tx];
    __syncthreads();
    int i = bi + ty, j = bj + tx;
    float a  = g_adj[(size_t)i * NN + j];
    float at = tileT[tx][ty];
    float v = fminf(a + at, 1.0f);
    if (i == j) v = 1.0f;
    g_nmb[(size_t)i * NN + j] = __float2half_rn(v);
}

__global__ void k_M() {
    size_t e = (size_t)blockIdx.x * blockDim.x + threadIdx.x;
    if (e >= (size_t)NN * NN) return;
    float c = g_common[e];
    float m = 0.f;
    if (g_adj[e] != 0.f && c > 1.0f) m = c * c;
    g_M[e] = m;
}

__global__ void k_degpart() {
    int d = blockIdx.x * blockDim.x + threadIdx.x;
    int chunk = blockIdx.y;
    float s = 0.f;
    int s0 = chunk * 128;
#pragma unroll 4
    for (int r = 0; r < 128; r++) s += g_M[(size_t)(s0 + r) * NN + d];
    g_degpart[chunk * NN + d] = s;
}

__global__ void k_dinv() {
    int d = blockIdx.x * blockDim.x + threadIdx.x;
    if (d >= NN) return;
    float s = 0.f;
#pragma unroll
    for (int c = 0; c < 16; c++) s += g_degpart[c * NN + d];
    float deg = s / g_max;
    g_dinv[d] = (deg > 0.f) ? rsqrtf(deg) : 0.f;
}

// transpose M -> WT3 [d][6144] = [Mh*16, Ml, M/128]
__global__ void k_wt3() {
    __shared__ float tile[32][33];
    int bs = blockIdx.y * 32, bd = blockIdx.x * 32;
    int tx = threadIdx.x, ty = threadIdx.y;
    tile[ty][tx] = g_M[(size_t)(bs + ty) * NN + bd + tx];
    __syncthreads();
    float v = tile[tx][ty];              // M[bs+tx][bd+ty]
    float mh = floorf(v * (1.0f / 2048.0f));     // exact
    float ml = v - mh * 2048.0f;                 // exact, < 2048
    size_t base = (size_t)(bd + ty) * N3 + bs + tx;
    g_WT3[base]          = __float2half_rn(mh * 16.0f);
    g_WT3[base + NN]     = __float2half_rn(ml);
    g_WT3[base + 2 * NN] = __float2half_rn(v * (1.0f / 128.0f));
}

// ---------------- HMMA fp16 GEMM: 128x128 tile, 8 warps, 4-stage cp.async ----------------
// C[m,n] = sum_k A[m*lda+k] * B[n*ldb+k]
enum { HEPI_ADJ = 0, HEPI_COMMON = 1, HEPI_OUT = 2, HEPI_Y3 = 3 };

#define TILE_B 10240                 // 128 rows * 80 B
#define STAGE_B (2 * TILE_B)         // A + B per stage
#define HSMEM_BYTES (4 * STAGE_B)    // 81920

template <int EPI>
__global__ void __launch_bounds__(256, 2)
hmma_gemm(const __half* __restrict__ A, const __half* __restrict__ B,
          float* __restrict__ C, int K, int lda, int ldb, int ldc,
          size_t strideB, int rowsPerZ,
          const float* __restrict__ gumbel, const float* __restrict__ bias)
{
    extern __shared__ char dsm[];
    const int tid = threadIdx.x, lane = tid & 31, wid = tid >> 5;
    const int wm = (wid & 3) * 32;
    const int wn = (wid >> 2) * 64;
    const int m0 = blockIdx.y * 128, n0 = blockIdx.x * 128;
    const int rowbase = rowsPerZ * blockIdx.z;

    B += strideB * blockIdx.z;
    const uint32_t s0 = smem_u32(dsm);

    float acc[2][8][4];
#pragma unroll
    for (int i = 0; i < 2; i++)
#pragma unroll
        for (int j = 0; j < 8; j++)
#pragma unroll
            for (int q = 0; q < 4; q++) acc[i][j][q] = 0.f;

    const int nch = K >> 5;
    const int lr = tid >> 2, lu = tid & 3;
    const __half* gA = A + (size_t)(m0 + lr) * lda + lu * 8;
    const __half* gB = B + (size_t)(n0 + lr) * ldb + lu * 8;
    const uint32_t sm_off = lr * 80 + lu * 16;

#define ISSUE(c) do {                                                      \
        int _buf = (c) & 3;                                                \
        uint32_t _da = s0 + _buf * STAGE_B + sm_off;                       \
        uint32_t _db = _da + TILE_B;                                       \
        const __half* _ga = gA + ((c) << 5);                               \
        const __half* _gb = gB + ((c) << 5);                               \
        CP16(_da, _ga); CP16(_db, _gb);                                    \
        CP16(_da + 64 * 80, _ga + (size_t)64 * lda);                       \
        CP16(_db + 64 * 80, _gb + (size_t)64 * ldb);                       \
        CP_COMMIT();                                                       \
    } while (0)

    ISSUE(0); ISSUE(1); ISSUE(2);

    for (int c = 0; c < nch; c++) {
        CP_WAIT2();
        __syncthreads();
        if (c + 3 < nch) ISSUE(c + 3);

        const uint32_t ba = s0 + (c & 3) * STAGE_B;
        const uint32_t bb = ba + TILE_B;
#pragma unroll
        for (int k16 = 0; k16 < 2; k16++) {
            uint32_t a[2][4], b[8][2];
            {
                int arow = wm + (lane & 15);
                int au = k16 * 2 + (lane >> 4);
                ldsm_x4(a[0][0], a[0][1], a[0][2], a[0][3], ba + arow * 80 + au * 16);
                ldsm_x4(a[1][0], a[1][1], a[1][2], a[1][3], ba + (arow + 16) * 80 + au * 16);
            }
#pragma unroll
            for (int np = 0; np < 4; np++) {
                int brow = wn + np * 16 + (lane & 7) + ((lane >> 4) << 3);
                int bu = k16 * 2 + ((lane >> 3) & 1);
                uint32_t r0, r1, r2, r3;
                ldsm_x4(r0, r1, r2, r3, bb + brow * 80 + bu * 16);
                b[2 * np][0] = r0; b[2 * np][1] = r1;
                b[2 * np + 1][0] = r2; b[2 * np + 1][1] = r3;
            }
#pragma unroll
            for (int mt = 0; mt < 2; mt++)
#pragma unroll
                for (int nt = 0; nt < 8; nt++)
                    mma16816(acc[mt][nt], a[mt], b[nt]);
        }
    }
#undef ISSUE

    // epilogue
    const int g = lane >> 2, tig = lane & 3;
    float lmax = 0.f;
#pragma unroll
    for (int mt = 0; mt < 2; mt++) {
#pragma unroll
        for (int half = 0; half < 2; half++) {
            int row = m0 + wm + mt * 16 + g + half * 8;
            int grow = rowbase + row;
#pragma unroll
            for (int nt = 0; nt < 8; nt++) {
                int col = n0 + wn + nt * 8 + 2 * tig;
                float v0 = acc[mt][nt][half * 2 + 0];
                float v1 = acc[mt][nt][half * 2 + 1];
                if (EPI == HEPI_ADJ) {
                    const float2* g2 = (const float2*)gumbel;
                    float2 ga = g2[(size_t)row * NN + col];
                    float2 gb = g2[(size_t)row * NN + col + 1];
                    float s0v = (v0 + 1.0f) * 0.5f;
                    float s1v = (v1 + 1.0f) * 0.5f;
                    float2 o;
                    o.x = (s0v + ga.x > (1.0f - s0v) + ga.y) ? 1.0f : 0.0f;
                    o.y = (s1v + gb.x > (1.0f - s1v) + gb.y) ? 1.0f : 0.0f;
                    *(float2*)&C[(size_t)row * ldc + col] = o;
                } else if (EPI == HEPI_COMMON) {
                    float2 o; o.x = v0; o.y = v1;
                    *(float2*)&C[(size_t)row * ldc + col] = o;
                    lmax = fmaxf(lmax, fmaxf(v0, v1));
                } else if (EPI == HEPI_OUT) {
                    float sc = 1.0f / g_max;
                    float bv = bias[row & (TT - 1)];
                    float2 o;
                    o.x = v0 * (g_dinv[col] * sc) + bv;
                    o.y = v1 * (g_dinv[col + 1] * sc) + bv;
                    *(float2*)&C[(size_t)row * ldc + col] = o;
                } else {  // HEPI_Y3: write [Yh*128, Yh, Yl*128] segments
                    float y0 = v0 * g_dinv[col];
                    float y1 = v1 * g_dinv[col + 1];
                    __half h0 = __float2half_rn(y0), h1 = __float2half_rn(y1);
                    float f0 = __half2float(h0), f1 = __half2float(h1);
                    size_t base = (size_t)grow * N3 + col;
                    __half2 seg0; seg0.x = __float2half_rn(f0 * 128.0f);
                                  seg0.y = __float2half_rn(f1 * 128.0f);
                    __half2 seg1; seg1.x = h0; seg1.y = h1;
                    __half2 seg2; seg2.x = __float2half_rn((y0 - f0) * 128.0f);
                                  seg2.y = __float2half_rn((y1 - f1) * 128.0f);
                    *(__half2*)&g_Y3[base]          = seg0;
                    *(__half2*)&g_Y3[base + NN]     = seg1;
                    *(__half2*)&g_Y3[base + 2*NN]   = seg2;
                }
            }
        }
    }
    if (EPI == HEPI_COMMON) {
        __syncthreads();
        float* red = (float*)dsm;
        red[tid] = lmax;
        __syncthreads();
        for (int s = 128; s > 0; s >>= 1) {
            if (tid < s) red[tid] = fmaxf(red[tid], red[tid + s]);
            __syncthreads();
        }
        if (tid == 0) atomicMax((int*)&g_max, __float_as_int(red[0]));
    }
}

// ---------------- launcher ----------------
extern "C" void kernel_launch(void* const* d_in, const int* in_sizes, int n_in,
                              void* d_out, int out_size)
{
    const float* x      = (const float*)d_in[0];   // [B,T,N]
    const float* weight = (const float*)d_in[1];   // [T,T]
    const float* bias   = (const float*)d_in[2];   // [T]
    const float* gumbel = (const float*)d_in[3];   // [N*N, 2]
    float* out = (float*)d_out;                    // [B,T,N] = [4096][2048]

    __half *p_xa3, *p_xb3, *p_nmb, *p_wt3, *p_y3, *p_w3, *p_xt3;
    float *p_adj, *p_common;
    cudaGetSymbolAddress((void**)&p_xa3,    g_xa3);
    cudaGetSymbolAddress((void**)&p_xb3,    g_xb3);
    cudaGetSymbolAddress((void**)&p_nmb,    g_nmb);
    cudaGetSymbolAddress((void**)&p_wt3,    g_WT3);
    cudaGetSymbolAddress((void**)&p_y3,     g_Y3);
    cudaGetSymbolAddress((void**)&p_w3,     g_w3);
    cudaGetSymbolAddress((void**)&p_xt3,    g_xT3);
    cudaGetSymbolAddress((void**)&p_adj,    g_adj);
    cudaGetSymbolAddress((void**)&p_common, g_common);

    cudaFuncSetAttribute(hmma_gemm<HEPI_ADJ>,    cudaFuncAttributeMaxDynamicSharedMemorySize, HSMEM_BYTES);
    cudaFuncSetAttribute(hmma_gemm<HEPI_COMMON>, cudaFuncAttributeMaxDynamicSharedMemorySize, HSMEM_BYTES);
    cudaFuncSetAttribute(hmma_gemm<HEPI_OUT>,    cudaFuncAttributeMaxDynamicSharedMemorySize, HSMEM_BYTES);
    cudaFuncSetAttribute(hmma_gemm<HEPI_Y3>,     cudaFuncAttributeMaxDynamicSharedMemorySize, HSMEM_BYTES);

    k_init<<<1, 1>>>();

    // mean over batch + row-normalize + fp16 hi/lo split (K-concat)
    k_colmean<<<(TT * NN) / 256, 256>>>(x);
    k_colnorm<<<NN / 256, 256>>>();
    {
        dim3 grid(NN / 32, TT / 32); dim3 blk(32, 32);
        k_writenorm<<<grid, blk>>>();
    }
    // weight + x splits (graph-independent)
    {
        dim3 grid(TT / 32, TT / 32); dim3 blk(32, 32);
        k_w3<<<grid, blk>>>(weight);
    }
    {
        dim3 grid(NN / 32, TT / 32, BB); dim3 blk(32, 32);
        k_xt3<<<grid, blk>>>(x);
    }

    // sim GEMM (3-term fp16 split, K=768) fused gumbel argmax -> adj
    {
        dim3 grid(NN / 128, NN / 128);
        hmma_gemm<HEPI_ADJ><<<grid, 256, HSMEM_BYTES>>>(
            p_xa3, p_xb3, p_adj, K3, K3, K3, NN, 0, 0, gumbel, nullptr);
    }

    // nmask = clip(adj + adj^T, 0, 1), diag=1, as fp16
    {
        dim3 grid(NN / 32, NN / 32); dim3 blk(32, 32);
        k_nmask<<<grid, blk>>>();
    }

    // common = nmask @ nmask^T (binary -> exact) + global max
    {
        dim3 grid(NN / 128, NN / 128);
        hmma_gemm<HEPI_COMMON><<<grid, 256, HSMEM_BYTES>>>(
            p_nmb, p_nmb, p_common, NN, NN, NN, NN, 0, 0, nullptr, nullptr);
    }

    // M = adj * (c>1) * c^2
    k_M<<<(int)(((size_t)NN * NN) / 256), 256>>>();

    // deg = (sum_s M)/max, dinv
    {
        dim3 grid(NN / 256, 16);
        k_degpart<<<grid, 256>>>();
    }
    k_dinv<<<NN / 256, 256>>>();

    // WT3 = transpose + exact integer split of M
    {
        dim3 grid(NN / 32, NN / 32); dim3 blk(32, 32);
        k_wt3<<<grid, blk>>>();
    }

    // Y3 via HMMA: Y[(b,o)][n] = sum_t w3[o][k] * xT3[b][n][k], epi scales by dinv & splits
    {
        dim3 grid(NN / 128, TT / 128, BB);
        hmma_gemm<HEPI_Y3><<<grid, 256, HSMEM_BYTES>>>(
            p_w3, p_xt3, nullptr, K3, K3, K3, 0,
            (size_t)NN * K3, TT, nullptr, nullptr);
    }

    // out = (Y' @ M) * dinv[d]/max + bias  (3-term fp16 K-concat, K=6144)
    {
        dim3 grid(NN / 128, (BB * TT) / 128);
        hmma_gemm<HEPI_OUT><<<grid, 256, HSMEM_BYTES>>>(
            p_y3, p_wt3, out, N3, N3, N3, NN, 0, 0, nullptr, bias);
    }
}

// round 5
// speedup vs baseline: 3.0488x; 1.1308x over previous
#include <cuda_runtime.h>
#include <cuda_fp16.h>
#include <cstdint>
#include <cstddef>

#define NN 2048      // nodes
#define BB 16        // batch
#define TT 256       // time/feature dim
#define K3 (3*TT)    // 768  (sim / Y3 split K)
#define K2 (2*NN)    // 4096 (out split K)

// ---------------- device scratch (no allocations allowed) ----------------
__device__ float g_xavg[TT * NN];                 // [t][n]
__device__ float g_invn[NN];
__device__ __half g_xa3[(size_t)NN * K3];         // [n][768] = [h, l, h]
__device__ __half g_xb3[(size_t)NN * K3];         // [n][768] = [h, h, l]
__device__ __half g_w3[(size_t)TT * K3];          // [o][768] = [wh, wl, wh]
__device__ __half g_xT3[(size_t)BB * NN * K3];    // [b][n][768] = [xh, xh, xl]
__device__ unsigned char g_adj8[(size_t)NN * NN]; // directed adjacency 0/1
__device__ signed char g_nm8[(size_t)NN * NN];    // nmask 0/1 (s8)
__device__ float g_common[(size_t)NN * NN];       // exact integer counts
__device__ __half g_WT2[(size_t)NN * K2];         // [d][4096] = [M/128, M/16384]
__device__ __half g_Y2[(size_t)BB * TT * K2];     // [4096][4096] = [Yh, Yl*128]
__device__ float g_degpart[16 * NN];
__device__ float g_dinv[NN];
__device__ int g_maxi;

// ---------------- PTX helpers (sm_80-level features only) ----------------
__device__ __forceinline__ uint32_t smem_u32(const void* p) {
    uint32_t a;
    asm("{ .reg .u64 t; cvta.to.shared.u64 t, %1; cvt.u32.u64 %0, t; }"
        : "=r"(a) : "l"(p));
    return a;
}

#define CP16(dst, src) \
    asm volatile("cp.async.cg.shared.global [%0], [%1], 16;" :: "r"(dst), "l"(src))
#define CP_COMMIT() asm volatile("cp.async.commit_group;" ::: "memory")
#define CP_WAIT2()  asm volatile("cp.async.wait_group 2;" ::: "memory")

__device__ __forceinline__ void ldsm_x4(uint32_t& r0, uint32_t& r1, uint32_t& r2,
                                        uint32_t& r3, uint32_t addr) {
    asm volatile("ldmatrix.sync.aligned.m8n8.x4.shared.b16 {%0,%1,%2,%3}, [%4];"
                 : "=r"(r0), "=r"(r1), "=r"(r2), "=r"(r3) : "r"(addr));
}

__device__ __forceinline__ void mma16816(float* c, const uint32_t* a, const uint32_t* b) {
    asm volatile(
        "mma.sync.aligned.m16n8k16.row.col.f32.f16.f16.f32 "
        "{%0,%1,%2,%3}, {%4,%5,%6,%7}, {%8,%9}, {%0,%1,%2,%3};"
        : "+f"(c[0]), "+f"(c[1]), "+f"(c[2]), "+f"(c[3])
        : "r"(a[0]), "r"(a[1]), "r"(a[2]), "r"(a[3]), "r"(b[0]), "r"(b[1]));
}

__device__ __forceinline__ void mma16832s8(int* c, const uint32_t* a, const uint32_t* b) {
    asm volatile(
        "mma.sync.aligned.m16n8k32.row.col.s32.s8.s8.s32 "
        "{%0,%1,%2,%3}, {%4,%5,%6,%7}, {%8,%9}, {%0,%1,%2,%3};"
        : "+r"(c[0]), "+r"(c[1]), "+r"(c[2]), "+r"(c[3])
        : "r"(a[0]), "r"(a[1]), "r"(a[2]), "r"(a[3]), "r"(b[0]), "r"(b[1]));
}

// ---------------- small kernels ----------------
__global__ void k_init() { g_maxi = 0; }

__global__ void k_colmean(const float* __restrict__ x) {
    int e = blockIdx.x * blockDim.x + threadIdx.x;    // over T*N, [t][n]
    if (e >= TT * NN) return;
    float s = 0.f;
#pragma unroll
    for (int b = 0; b < BB; b++) s += x[(size_t)b * TT * NN + e];
    g_xavg[e] = s * (1.0f / BB);
}

__global__ void k_colnorm() {
    int n = blockIdx.x * blockDim.x + threadIdx.x;
    if (n >= NN) return;
    float s = 0.f;
#pragma unroll 4
    for (int t = 0; t < TT; t++) { float v = g_xavg[t * NN + n]; s = fmaf(v, v, s); }
    float nrm = sqrtf(s);
    g_invn[n] = 1.0f / fmaxf(nrm, 1e-12f);
}

__global__ void k_writenorm() {   // grid (NN/32, TT/32), block (32,32)
    __shared__ float tile[32][33];
    int n0 = blockIdx.x * 32, t0 = blockIdx.y * 32;
    int tx = threadIdx.x, ty = threadIdx.y;
    tile[ty][tx] = g_xavg[(t0 + ty) * NN + n0 + tx] * g_invn[n0 + tx];
    __syncthreads();
    int n = n0 + ty, t = t0 + tx;
    float v = tile[tx][ty];
    __half h = __float2half_rn(v);
    __half l = __float2half_rn(v - __half2float(h));
    size_t base = (size_t)n * K3;
    g_xa3[base + t] = h; g_xa3[base + TT + t] = l; g_xa3[base + 2 * TT + t] = h;
    g_xb3[base + t] = h; g_xb3[base + TT + t] = h; g_xb3[base + 2 * TT + t] = l;
}

// weight [t][o] -> w3 [o][768] = [wh, wl, wh]
__global__ void k_w3(const float* __restrict__ w) {  // grid (8,8), block (32,32)
    __shared__ float tile[32][33];
    int o0 = blockIdx.x * 32, t0 = blockIdx.y * 32;
    int tx = threadIdx.x, ty = threadIdx.y;
    tile[ty][tx] = w[(t0 + ty) * TT + o0 + tx];
    __syncthreads();
    int o = o0 + ty, t = t0 + tx;
    float v = tile[tx][ty];
    __half h = __float2half_rn(v);
    __half l = __float2half_rn(v - __half2float(h));
    size_t base = (size_t)o * K3;
    g_w3[base + t] = h; g_w3[base + TT + t] = l; g_w3[base + 2 * TT + t] = h;
}

// x [b][t][n] -> xT3 [b][n][768] = [xh, xh, xl]
__global__ void k_xt3(const float* __restrict__ x) { // grid (NN/32, TT/32, BB), block (32,32)
    __shared__ float tile[32][33];
    int n0 = blockIdx.x * 32, t0 = blockIdx.y * 32, z = blockIdx.z;
    int tx = threadIdx.x, ty = threadIdx.y;
    tile[ty][tx] = x[(size_t)z * TT * NN + (t0 + ty) * NN + n0 + tx];
    __syncthreads();
    int n = n0 + ty, t = t0 + tx;
    float v = tile[tx][ty];
    __half h = __float2half_rn(v);
    __half l = __float2half_rn(v - __half2float(h));
    size_t base = ((size_t)z * NN + n) * K3;
    g_xT3[base + t] = h; g_xT3[base + TT + t] = h; g_xT3[base + 2 * TT + t] = l;
}

__global__ void k_nmask() {       // grid (64,64), block (32,32)
    __shared__ unsigned char tileT[32][33];
    int bi = blockIdx.y * 32, bj = blockIdx.x * 32;
    int tx = threadIdx.x, ty = threadIdx.y;
    tileT[ty][tx] = g_adj8[(size_t)(bj + ty) * NN + bi + tx];
    __syncthreads();
    int i = bi + ty, j = bj + tx;
    int a  = g_adj8[(size_t)i * NN + j];
    int at = tileT[tx][ty];
    int v = (a + at > 0) ? 1 : 0;
    if (i == j) v = 1;
    g_nm8[(size_t)i * NN + j] = (signed char)v;
}

// deg partial: S[d] partial over 128 source rows; M = adj*(c>1)*c^2
__global__ void k_degpart() {
    int d = blockIdx.x * blockDim.x + threadIdx.x;
    int chunk = blockIdx.y;
    float s = 0.f;
    int s0 = chunk * 128;
#pragma unroll 4
    for (int r = 0; r < 128; r++) {
        size_t e = (size_t)(s0 + r) * NN + d;
        float c = g_common[e];
        if (g_adj8[e] != 0 && c > 1.0f) s += c * c;
    }
    g_degpart[chunk * NN + d] = s;
}

__global__ void k_dinv() {
    int d = blockIdx.x * blockDim.x + threadIdx.x;
    if (d >= NN) return;
    float s = 0.f;
#pragma unroll
    for (int c = 0; c < 16; c++) s += g_degpart[c * NN + d];
    float deg = s / (float)g_maxi;
    g_dinv[d] = (deg > 0.f) ? rsqrtf(deg) : 0.f;
}

// WT2[d][s] = [fp16(M/128), fp16(M/16384)], M = adjT[d,s]*(c>1)*c^2, c = common[d][s] (symmetric)
__global__ void k_wt2() {         // grid (64,64): x = s-tile, y = d-tile; block (32,32)
    __shared__ unsigned char tileA[32][33];
    int bs = blockIdx.x * 32, bd = blockIdx.y * 32;
    int tx = threadIdx.x, ty = threadIdx.y;
    // adj[s][d] tile, transposed read later
    tileA[ty][tx] = g_adj8[(size_t)(bs + ty) * NN + bd + tx];
    __syncthreads();
    int d = bd + ty, s = bs + tx;
    float c = g_common[(size_t)d * NN + s];      // = common[s][d]
    float m = 0.f;
    if (tileA[tx][ty] != 0 && c > 1.0f) m = c * c;
    size_t base = (size_t)d * K2 + s;
    g_WT2[base]      = __float2half_rn(m * (1.0f / 128.0f));
    g_WT2[base + NN] = __float2half_rn(m * (1.0f / 16384.0f));
}

// ---------------- HMMA fp16 GEMM: 128x128 tile, 8 warps, 4-stage cp.async ----------------
enum { HEPI_ADJ = 0, HEPI_OUT = 1, HEPI_Y2 = 2 };

#define TILE_B 10240                 // 128 rows * 80 B
#define STAGE_B (2 * TILE_B)
#define HSMEM_BYTES (4 * STAGE_B)    // 81920

template <int EPI>
__global__ void __launch_bounds__(256, 2)
hmma_gemm(const __half* __restrict__ A, const __half* __restrict__ B,
          float* __restrict__ C, int K, int lda, int ldb, int ldc,
          size_t strideB, int rowsPerZ,
          const float* __restrict__ gumbel, const float* __restrict__ bias)
{
    extern __shared__ char dsm[];
    const int tid = threadIdx.x, lane = tid & 31, wid = tid >> 5;
    const int wm = (wid & 3) * 32;
    const int wn = (wid >> 2) * 64;
    const int m0 = blockIdx.y * 128, n0 = blockIdx.x * 128;
    const int rowbase = rowsPerZ * blockIdx.z;

    B += strideB * blockIdx.z;
    const uint32_t s0 = smem_u32(dsm);

    float acc[2][8][4];
#pragma unroll
    for (int i = 0; i < 2; i++)
#pragma unroll
        for (int j = 0; j < 8; j++)
#pragma unroll
            for (int q = 0; q < 4; q++) acc[i][j][q] = 0.f;

    const int nch = K >> 5;
    const int lr = tid >> 2, lu = tid & 3;
    const __half* gA = A + (size_t)(m0 + lr) * lda + lu * 8;
    const __half* gB = B + (size_t)(n0 + lr) * ldb + lu * 8;
    const uint32_t sm_off = lr * 80 + lu * 16;

#define ISSUE(c) do {                                                      \
        int _buf = (c) & 3;                                                \
        uint32_t _da = s0 + _buf * STAGE_B + sm_off;                       \
        uint32_t _db = _da + TILE_B;                                       \
        const __half* _ga = gA + ((size_t)(c) << 5);                       \
        const __half* _gb = gB + ((size_t)(c) << 5);                       \
        CP16(_da, _ga); CP16(_db, _gb);                                    \
        CP16(_da + 64 * 80, _ga + (size_t)64 * lda);                       \
        CP16(_db + 64 * 80, _gb + (size_t)64 * ldb);                       \
        CP_COMMIT();                                                       \
    } while (0)

    ISSUE(0); ISSUE(1); ISSUE(2);

    for (int c = 0; c < nch; c++) {
        CP_WAIT2();
        __syncthreads();
        if (c + 3 < nch) ISSUE(c + 3);

        const uint32_t ba = s0 + (c & 3) * STAGE_B;
        const uint32_t bb = ba + TILE_B;
#pragma unroll
        for (int k16 = 0; k16 < 2; k16++) {
            uint32_t a[2][4], b[8][2];
            {
                int arow = wm + (lane & 15);
                int au = k16 * 2 + (lane >> 4);
                ldsm_x4(a[0][0], a[0][1], a[0][2], a[0][3], ba + arow * 80 + au * 16);
                ldsm_x4(a[1][0], a[1][1], a[1][2], a[1][3], ba + (arow + 16) * 80 + au * 16);
            }
#pragma unroll
            for (int np = 0; np < 4; np++) {
                int brow = wn + np * 16 + (lane & 7) + ((lane >> 4) << 3);
                int bu = k16 * 2 + ((lane >> 3) & 1);
                uint32_t r0, r1, r2, r3;
                ldsm_x4(r0, r1, r2, r3, bb + brow * 80 + bu * 16);
                b[2 * np][0] = r0; b[2 * np][1] = r1;
                b[2 * np + 1][0] = r2; b[2 * np + 1][1] = r3;
            }
#pragma unroll
            for (int mt = 0; mt < 2; mt++)
#pragma unroll
                for (int nt = 0; nt < 8; nt++)
                    mma16816(acc[mt][nt], a[mt], b[nt]);
        }
    }
#undef ISSUE

    // epilogue
    const int g = lane >> 2, tig = lane & 3;
#pragma unroll
    for (int mt = 0; mt < 2; mt++) {
#pragma unroll
        for (int half = 0; half < 2; half++) {
            int row = m0 + wm + mt * 16 + g + half * 8;
            int grow = rowbase + row;
#pragma unroll
            for (int nt = 0; nt < 8; nt++) {
                int col = n0 + wn + nt * 8 + 2 * tig;
                float v0 = acc[mt][nt][half * 2 + 0];
                float v1 = acc[mt][nt][half * 2 + 1];
                if (EPI == HEPI_ADJ) {
                    const float2* g2 = (const float2*)gumbel;
                    float2 ga = g2[(size_t)row * NN + col];
                    float2 gb = g2[(size_t)row * NN + col + 1];
                    float s0v = (v0 + 1.0f) * 0.5f;
                    float s1v = (v1 + 1.0f) * 0.5f;
                    uchar2 o;
                    o.x = (s0v + ga.x > (1.0f - s0v) + ga.y) ? 1 : 0;
                    o.y = (s1v + gb.x > (1.0f - s1v) + gb.y) ? 1 : 0;
                    *(uchar2*)&g_adj8[(size_t)row * NN + col] = o;
                } else if (EPI == HEPI_OUT) {
                    float sc = 128.0f / (float)g_maxi;
                    float bv = bias[row & (TT - 1)];
                    float2 o;
                    o.x = v0 * (g_dinv[col] * sc) + bv;
                    o.y = v1 * (g_dinv[col + 1] * sc) + bv;
                    *(float2*)&C[(size_t)row * ldc + col] = o;
                } else {  // HEPI_Y2: write [Yh, Yl*128] segments
                    float y0 = v0 * g_dinv[col];
                    float y1 = v1 * g_dinv[col + 1];
                    __half h0 = __float2half_rn(y0), h1 = __float2half_rn(y1);
                    float f0 = __half2float(h0), f1 = __half2float(h1);
                    size_t base = (size_t)grow * K2 + col;
                    __half2 seg0; seg0.x = h0; seg0.y = h1;
                    __half2 seg1; seg1.x = __float2half_rn((y0 - f0) * 128.0f);
                                  seg1.y = __float2half_rn((y1 - f1) * 128.0f);
                    *(__half2*)&g_Y2[base]      = seg0;
                    *(__half2*)&g_Y2[base + NN] = seg1;
                }
            }
        }
    }
}

// ---------------- int8 MMA GEMM for common = nm @ nm^T (exact) ----------------
__global__ void __launch_bounds__(256, 2)
i8gemm_common(const signed char* __restrict__ A, const signed char* __restrict__ B,
              float* __restrict__ C, int K, int lda, int ldb, int ldc)
{
    extern __shared__ char dsm[];
    const int tid = threadIdx.x, lane = tid & 31, wid = tid >> 5;
    const int wm = (wid & 3) * 32;
    const int wn = (wid >> 2) * 64;
    const int m0 = blockIdx.y * 128, n0 = blockIdx.x * 128;

    const uint32_t s0 = smem_u32(dsm);

    int acc[2][8][4];
#pragma unroll
    for (int i = 0; i < 2; i++)
#pragma unroll
        for (int j = 0; j < 8; j++)
#pragma unroll
            for (int q = 0; q < 4; q++) acc[i][j][q] = 0;

    const int nch = K >> 6;                 // 64 int8 per chunk
    const int lr = tid >> 2, lu = tid & 3;  // row, 16B unit (4 per 64B row)
    const signed char* gA = A + (size_t)(m0 + lr) * lda + lu * 16;
    const signed char* gB = B + (size_t)(n0 + lr) * ldb + lu * 16;
    const uint32_t sm_off = lr * 80 + lu * 16;

#define ISSUE8(c) do {                                                     \
        int _buf = (c) & 3;                                                \
        uint32_t _da = s0 + _buf * STAGE_B + sm_off;                       \
        uint32_t _db = _da + TILE_B;                                       \
        const signed char* _ga = gA + ((size_t)(c) << 6);                  \
        const signed char* _gb = gB + ((size_t)(c) << 6);                  \
        CP16(_da, _ga); CP16(_db, _gb);                                    \
        CP16(_da + 64 * 80, _ga + (size_t)64 * lda);                       \
        CP16(_db + 64 * 80, _gb + (size_t)64 * ldb);                       \
        CP_COMMIT();                                                       \
    } while (0)

    ISSUE8(0); ISSUE8(1); ISSUE8(2);

    for (int c = 0; c < nch; c++) {
        CP_WAIT2();
        __syncthreads();
        if (c + 3 < nch) ISSUE8(c + 3);

        const uint32_t ba = s0 + (c & 3) * STAGE_B;
        const uint32_t bb = ba + TILE_B;
#pragma unroll
        for (int k32 = 0; k32 < 2; k32++) {
            uint32_t a[2][4], b[8][2];
            {
                int arow = wm + (lane & 15);
                int au = k32 * 2 + (lane >> 4);
                ldsm_x4(a[0][0], a[0][1], a[0][2], a[0][3], ba + arow * 80 + au * 16);
                ldsm_x4(a[1][0], a[1][1], a[1][2], a[1][3], ba + (arow + 16) * 80 + au * 16);
            }
#pragma unroll
            for (int np = 0; np < 4; np++) {
                int brow = wn + np * 16 + (lane & 7) + ((lane >> 4) << 3);
                int bu = k32 * 2 + ((lane >> 3) & 1);
                uint32_t r0, r1, r2, r3;
                ldsm_x4(r0, r1, r2, r3, bb + brow * 80 + bu * 16);
                b[2 * np][0] = r0; b[2 * np][1] = r1;
                b[2 * np + 1][0] = r2; b[2 * np + 1][1] = r3;
            }
#pragma unroll
            for (int mt = 0; mt < 2; mt++)
#pragma unroll
                for (int nt = 0; nt < 8; nt++)
                    mma16832s8(acc[mt][nt], a[mt], b[nt]);
        }
    }
#undef ISSUE8

    const int g = lane >> 2, tig = lane & 3;
    int lmax = 0;
#pragma unroll
    for (int mt = 0; mt < 2; mt++) {
#pragma unroll
        for (int half = 0; half < 2; half++) {
            int row = m0 + wm + mt * 16 + g + half * 8;
#pragma unroll
            for (int nt = 0; nt < 8; nt++) {
                int col = n0 + wn + nt * 8 + 2 * tig;
                int v0 = acc[mt][nt][half * 2 + 0];
                int v1 = acc[mt][nt][half * 2 + 1];
                float2 o; o.x = (float)v0; o.y = (float)v1;
                *(float2*)&C[(size_t)row * ldc + col] = o;
                lmax = max(lmax, max(v0, v1));
            }
        }
    }
    __syncthreads();
    int* red = (int*)dsm;
    red[tid] = lmax;
    __syncthreads();
    for (int s = 128; s > 0; s >>= 1) {
        if (tid < s) red[tid] = max(red[tid], red[tid + s]);
        __syncthreads();
    }
    if (tid == 0) atomicMax(&g_maxi, red[0]);
}

// ---------------- launcher ----------------
extern "C" void kernel_launch(void* const* d_in, const int* in_sizes, int n_in,
                              void* d_out, int out_size)
{
    const float* x      = (const float*)d_in[0];   // [B,T,N]
    const float* weight = (const float*)d_in[1];   // [T,T]
    const float* bias   = (const float*)d_in[2];   // [T]
    const float* gumbel = (const float*)d_in[3];   // [N*N, 2]
    float* out = (float*)d_out;                    // [B,T,N] = [4096][2048]

    __half *p_xa3, *p_xb3, *p_wt2, *p_y2, *p_w3, *p_xt3;
    signed char* p_nm8;
    float* p_common;
    cudaGetSymbolAddress((void**)&p_xa3,    g_xa3);
    cudaGetSymbolAddress((void**)&p_xb3,    g_xb3);
    cudaGetSymbolAddress((void**)&p_nm8,    g_nm8);
    cudaGetSymbolAddress((void**)&p_wt2,    g_WT2);
    cudaGetSymbolAddress((void**)&p_y2,     g_Y2);
    cudaGetSymbolAddress((void**)&p_w3,     g_w3);
    cudaGetSymbolAddress((void**)&p_xt3,    g_xT3);
    cudaGetSymbolAddress((void**)&p_common, g_common);

    cudaFuncSetAttribute(hmma_gemm<HEPI_ADJ>, cudaFuncAttributeMaxDynamicSharedMemorySize, HSMEM_BYTES);
    cudaFuncSetAttribute(hmma_gemm<HEPI_OUT>, cudaFuncAttributeMaxDynamicSharedMemorySize, HSMEM_BYTES);
    cudaFuncSetAttribute(hmma_gemm<HEPI_Y2>,  cudaFuncAttributeMaxDynamicSharedMemorySize, HSMEM_BYTES);
    cudaFuncSetAttribute(i8gemm_common,       cudaFuncAttributeMaxDynamicSharedMemorySize, HSMEM_BYTES);

    k_init<<<1, 1>>>();

    // mean over batch + row-normalize + fp16 hi/lo split (K-concat)
    k_colmean<<<(TT * NN) / 256, 256>>>(x);
    k_colnorm<<<NN / 256, 256>>>();
    {
        dim3 grid(NN / 32, TT / 32); dim3 blk(32, 32);
        k_writenorm<<<grid, blk>>>();
    }
    {
        dim3 grid(TT / 32, TT / 32); dim3 blk(32, 32);
        k_w3<<<grid, blk>>>(weight);
    }
    {
        dim3 grid(NN / 32, TT / 32, BB); dim3 blk(32, 32);
        k_xt3<<<grid, blk>>>(x);
    }

    // sim GEMM (3-term fp16 split, K=768) fused gumbel argmax -> adj8
    {
        dim3 grid(NN / 128, NN / 128);
        hmma_gemm<HEPI_ADJ><<<grid, 256, HSMEM_BYTES>>>(
            p_xa3, p_xb3, nullptr, K3, K3, K3, 0, 0, 0, gumbel, nullptr);
    }

    // nmask (s8, 0/1)
    {
        dim3 grid(NN / 32, NN / 32); dim3 blk(32, 32);
        k_nmask<<<grid, blk>>>();
    }

    // common = nm @ nm^T, exact int8 MMA + global max (int atomic)
    {
        dim3 grid(NN / 128, NN / 128);
        i8gemm_common<<<grid, 256, HSMEM_BYTES>>>(p_nm8, p_nm8, p_common, NN, NN, NN, NN);
    }

    // deg partials, dinv
    {
        dim3 grid(NN / 256, 16);
        k_degpart<<<grid, 256>>>();
    }
    k_dinv<<<NN / 256, 256>>>();

    // WT2 = transposed M, 2-segment fp16
    {
        dim3 grid(NN / 32, NN / 32); dim3 blk(32, 32);
        k_wt2<<<grid, blk>>>();
    }

    // Y2 via HMMA: Y[(b,o)][n] = sum_t w3[o][k] * xT3[b][n][k], epi scales by dinv & 2-splits
    {
        dim3 grid(NN / 128, TT / 128, BB);
        hmma_gemm<HEPI_Y2><<<grid, 256, HSMEM_BYTES>>>(
            p_w3, p_xt3, nullptr, K3, K3, K3, 0,
            (size_t)NN * K3, TT, nullptr, nullptr);
    }

    // out = (Y' @ M) * 128*dinv[d]/max + bias  (2-term fp16 K-concat, K=4096)
    {
        dim3 grid(NN / 128, (BB * TT) / 128);
        hmma_gemm<HEPI_OUT><<<grid, 256, HSMEM_BYTES>>>(
            p_y2, p_wt2, out, K2, K2, K2, NN, 0, 0, nullptr, bias);
    }
}